// round 3
// baseline (speedup 1.0000x reference)
#include <cuda_runtime.h>
#include <math.h>

#define NB   8
#define NH   16
#define LQ   128
#define LC   4096
#define DD   1024
#define HL   (NH * LQ)   // 2048
#define TOPK 5
#define EPS  1e-8f
#define NEG_HUGE (-3.4e38f)

// Scratch (allocation-free rule: __device__ globals)
__device__ float g_avg[NB * LC];    // sums of attn over (h, lq)
__device__ float g_qvec[NB * DD];   // sums of question over lq
__device__ float g_loss_sum;
__device__ int   g_done;

// ---------------------------------------------------------------------------
// 0. Zero scratch (graph replays require re-zeroing every launch)
// ---------------------------------------------------------------------------
__global__ void zero_kernel() {
    int i = blockIdx.x * blockDim.x + threadIdx.x;
    if (i < NB * LC) g_avg[i] = 0.0f;
    if (i < NB * DD) g_qvec[i] = 0.0f;
    if (i == 0) { g_loss_sum = 0.0f; g_done = 0; }
}

// ---------------------------------------------------------------------------
// 1. Sum cross_attn_weights over (h, lq)  ->  g_avg[b, lc]   (256 MB read)
// grid: (4, 32, 8) = 1024 blocks, 256 thr, float4 coalesced along Lc
// ---------------------------------------------------------------------------
__global__ void attn_reduce(const float4* __restrict__ w) {
    const int cchunk = blockIdx.x;           // 0..3
    const int seg    = blockIdx.y;           // 0..31
    const int b      = blockIdx.z;           // 0..7
    const int lc4    = cchunk * 256 + threadIdx.x;
    const int ROWS   = HL / 32;              // 64

    float4 acc = make_float4(0.f, 0.f, 0.f, 0.f);
    size_t base = ((size_t)b * HL + (size_t)seg * ROWS) * (LC / 4) + lc4;

    #pragma unroll 16
    for (int r = 0; r < ROWS; r++) {
        float4 v = w[base + (size_t)r * (LC / 4)];
        acc.x += v.x; acc.y += v.y; acc.z += v.z; acc.w += v.w;
    }

    float* dst = &g_avg[b * LC + lc4 * 4];
    atomicAdd(dst + 0, acc.x);
    atomicAdd(dst + 1, acc.y);
    atomicAdd(dst + 2, acc.z);
    atomicAdd(dst + 3, acc.w);
}

// ---------------------------------------------------------------------------
// 2. Sum question_emb over lq -> g_qvec[b, d]   (4 MB read)
// ---------------------------------------------------------------------------
__global__ void qvec_reduce(const float4* __restrict__ q) {
    const int seg = blockIdx.x;   // 0..7 (16 lq rows each)
    const int b   = blockIdx.y;
    const int tid = threadIdx.x;

    float4 acc = make_float4(0.f, 0.f, 0.f, 0.f);
    size_t base = ((size_t)b * LQ + (size_t)seg * 16) * (DD / 4) + tid;

    #pragma unroll
    for (int r = 0; r < 16; r++) {
        float4 v = q[base + (size_t)r * (DD / 4)];
        acc.x += v.x; acc.y += v.y; acc.z += v.z; acc.w += v.w;
    }

    float* dst = &g_qvec[b * DD + tid * 4];
    atomicAdd(dst + 0, acc.x);
    atomicAdd(dst + 1, acc.y);
    atomicAdd(dst + 2, acc.z);
    atomicAdd(dst + 3, acc.w);
}

// ---------------------------------------------------------------------------
// helpers: warp reductions
// ---------------------------------------------------------------------------
__device__ __forceinline__ void warp_argmax(float& v, int& i) {
    #pragma unroll
    for (int off = 16; off > 0; off >>= 1) {
        float v2 = __shfl_down_sync(0xffffffffu, v, off);
        int   i2 = __shfl_down_sync(0xffffffffu, i, off);
        if (v2 > v || (v2 == v && i2 < i)) { v = v2; i = i2; }
    }
}
__device__ __forceinline__ float warp_sum(float v) {
    #pragma unroll
    for (int off = 16; off > 0; off >>= 1)
        v += __shfl_down_sync(0xffffffffu, v, off);
    return v;
}

// ---------------------------------------------------------------------------
// 3. Fused tail: per-batch top-5 (min-index tie-break, matches jax top_k),
//    mean-q cosine vs gathered rows, and global mean written by last block.
// grid: NB blocks x 1024 threads (32 warps)
// ---------------------------------------------------------------------------
__global__ void __launch_bounds__(1024, 1)
tail_kernel(const float* __restrict__ ctx, float* __restrict__ out) {
    __shared__ float s_attn[LC];        // 16 KB
    __shared__ float s_q[DD];           // 4 KB
    __shared__ float s_wv[32];
    __shared__ int   s_wi[32];
    __shared__ float s_wd[32], s_wc[32];
    __shared__ int   s_top[TOPK];
    __shared__ float s_qnorm;

    const int b    = blockIdx.x;
    const int tid  = threadIdx.x;
    const int lane = tid & 31;
    const int wid  = tid >> 5;

    // --- mean question vector + its norm -------------------------------
    float qm = g_qvec[b * DD + tid] * (1.0f / (float)LQ);
    s_q[tid] = qm;
    {
        float ps = warp_sum(qm * qm);
        if (lane == 0) s_wv[wid] = ps;
    }

    // --- stage avg_attn (sums; scale-invariant ordering) ----------------
    #pragma unroll
    for (int j = 0; j < 4; j++)
        s_attn[tid + j * 1024] = g_avg[b * LC + tid + j * 1024];
    __syncthreads();

    if (wid == 0) {
        float v = s_wv[lane];
        v = warp_sum(v);
        if (lane == 0) s_qnorm = fmaxf(sqrtf(v), EPS);
    }

    // --- 5 rounds of argmax with min-index tie-break ---------------------
    for (int k = 0; k < TOPK; k++) {
        float bv = NEG_HUGE; int bi = 0;
        #pragma unroll
        for (int j = 0; j < 4; j++) {
            int i = tid + j * 1024;           // ascending i per thread
            float v = s_attn[i];
            if (v > bv) { bv = v; bi = i; }   // strict > keeps smallest i
        }
        warp_argmax(bv, bi);
        if (lane == 0) { s_wv[wid] = bv; s_wi[wid] = bi; }
        __syncthreads();
        if (wid == 0) {
            float v = s_wv[lane]; int i = s_wi[lane];
            warp_argmax(v, i);
            if (lane == 0) { s_top[k] = i; s_attn[i] = NEG_HUGE; }
        }
        __syncthreads();
    }

    // --- prefetch all 5 context rows in parallel (one DRAM round-trip) ---
    float cv[TOPK];
    #pragma unroll
    for (int k = 0; k < TOPK; k++)
        cv[k] = ctx[((size_t)b * LC + (size_t)s_top[k]) * DD + tid];

    // --- cosine similarities ---------------------------------------------
    const float qv = s_q[tid];
    float loss = 0.0f;
    #pragma unroll
    for (int k = 0; k < TOPK; k++) {
        float d  = warp_sum(cv[k] * qv);
        float cn = warp_sum(cv[k] * cv[k]);
        if (lane == 0) { s_wd[wid] = d; s_wc[wid] = cn; }
        __syncthreads();
        if (wid == 0) {
            float dd = warp_sum(s_wd[lane]);
            float cc = warp_sum(s_wc[lane]);
            if (lane == 0) {
                float cnorm = fmaxf(sqrtf(cc), EPS);
                loss += 1.0f - dd / (s_qnorm * cnorm);
            }
        }
        __syncthreads();
    }

    // --- fold into global mean; last block writes out ---------------------
    if (tid == 0) {
        atomicAdd(&g_loss_sum, loss);
        __threadfence();
        int t = atomicAdd(&g_done, 1);
        if (t == NB - 1)
            out[0] = g_loss_sum / (float)(NB * TOPK);
    }
}

// ---------------------------------------------------------------------------
extern "C" void kernel_launch(void* const* d_in, const int* in_sizes, int n_in,
                              void* d_out, int out_size) {
    const float* q   = (const float*)d_in[0];  // question_emb  [8,128,1024]
    const float* ctx = (const float*)d_in[1];  // context_emb   [8,4096,1024]
    const float* w   = (const float*)d_in[2];  // cross_attn    [8,16,128,4096]

    zero_kernel<<<(NB * LC + 255) / 256, 256>>>();

    dim3 g1(LC / 1024, 32, NB);   // 1024 blocks
    attn_reduce<<<g1, 256>>>((const float4*)w);

    dim3 g2(8, NB);               // 64 blocks
    qvec_reduce<<<g2, 256>>>((const float4*)q);

    tail_kernel<<<NB, 1024>>>(ctx, (float*)d_out);
}

// round 4
// speedup vs baseline: 1.1099x; 1.1099x over previous
#include <cuda_runtime.h>
#include <math.h>

#define NB   8
#define NH   16
#define LQ   128
#define LC   4096
#define DD   1024
#define HL   (NH * LQ)   // 2048
#define TOPK 5
#define EPS  1e-8f

// Scratch (__device__ globals; zero-initialized at load, re-zeroed by tail
// each run so graph replays are self-consistent with no zero_kernel).
__device__ float g_avg[NB * LC];
__device__ float g_qvec[NB * DD];
__device__ float g_loss_sum;
__device__ int   g_done;

// ---------------------------------------------------------------------------
// helpers
// ---------------------------------------------------------------------------
__device__ __forceinline__ float warp_sum(float v) {
    #pragma unroll
    for (int off = 16; off > 0; off >>= 1)
        v += __shfl_down_sync(0xffffffffu, v, off);
    return v;
}
__device__ __forceinline__ unsigned long long warp_max64(unsigned long long k) {
    #pragma unroll
    for (int off = 16; off > 0; off >>= 1) {
        unsigned long long o = __shfl_down_sync(0xffffffffu, k, off);
        if (o > k) k = o;
    }
    return k;
}
// orderable mapping: preserves float total order as unsigned compare
__device__ __forceinline__ unsigned ord(float f) {
    unsigned fb = __float_as_uint(f);
    unsigned m  = (unsigned)((int)fb >> 31);
    return fb ^ (m | 0x80000000u);
}

// ---------------------------------------------------------------------------
// 1. Fused reduce: blocks [0,1024) sum attn over (h,lq); blocks [1024,1088)
//    sum question over lq. Both atomicAdd into pre-zeroed scratch.
// ---------------------------------------------------------------------------
__global__ void __launch_bounds__(256)
fused_reduce(const float4* __restrict__ w, const float4* __restrict__ q) {
    const int id = blockIdx.x;

    if (id < 1024) {                       // ---- attn part (256 MB read) ----
        const int b      = id >> 7;        // /128
        const int rem    = id & 127;
        const int seg    = rem >> 2;       // 0..31
        const int cchunk = rem & 3;        // 0..3
        const int lc4    = cchunk * 256 + threadIdx.x;
        const int ROWS   = HL / 32;        // 64

        float4 acc = make_float4(0.f, 0.f, 0.f, 0.f);
        size_t base = ((size_t)b * HL + (size_t)seg * ROWS) * (LC / 4) + lc4;

        #pragma unroll 16
        for (int r = 0; r < ROWS; r++) {
            float4 v = w[base + (size_t)r * (LC / 4)];
            acc.x += v.x; acc.y += v.y; acc.z += v.z; acc.w += v.w;
        }
        float* dst = &g_avg[b * LC + lc4 * 4];
        atomicAdd(dst + 0, acc.x);
        atomicAdd(dst + 1, acc.y);
        atomicAdd(dst + 2, acc.z);
        atomicAdd(dst + 3, acc.w);
    } else {                               // ---- question part (4 MB) ----
        const int id2 = id - 1024;
        const int b   = id2 >> 3;
        const int seg = id2 & 7;           // 16 lq rows each
        const int tid = threadIdx.x;

        float4 acc = make_float4(0.f, 0.f, 0.f, 0.f);
        size_t base = ((size_t)b * LQ + (size_t)seg * 16) * (DD / 4) + tid;

        #pragma unroll
        for (int r = 0; r < 16; r++) {
            float4 v = q[base + (size_t)r * (DD / 4)];
            acc.x += v.x; acc.y += v.y; acc.z += v.z; acc.w += v.w;
        }
        float* dst = &g_qvec[b * DD + tid * 4];
        atomicAdd(dst + 0, acc.x);
        atomicAdd(dst + 1, acc.y);
        atomicAdd(dst + 2, acc.z);
        atomicAdd(dst + 3, acc.w);
    }
}

// ---------------------------------------------------------------------------
// 2. Tail: per-batch top-5 (min-index tie-break = jax top_k), cosine vs mean
//    question vector, global mean by ticket. Also resets all scratch.
// grid: NB x 256 threads (8 warps)
// ---------------------------------------------------------------------------
__global__ void __launch_bounds__(256, 1)
tail_kernel(const float* __restrict__ ctx, float* __restrict__ out) {
    __shared__ float              s_attn[LC];     // 16 KB
    __shared__ float              s_wv[8];
    __shared__ unsigned long long s_key[8];
    __shared__ int                s_top[TOPK];
    __shared__ float              s_red[2 * TOPK][8];

    const int b    = blockIdx.x;
    const int tid  = threadIdx.x;
    const int lane = tid & 31;
    const int wid  = tid >> 5;
    const float4 zero4 = make_float4(0.f, 0.f, 0.f, 0.f);

    // --- mean question vector (registers only; thread t owns dims 4t..4t+3)
    float4 q4 = reinterpret_cast<const float4*>(g_qvec)[b * (DD / 4) + tid];
    const float inv = 1.0f / (float)LQ;
    q4.x *= inv; q4.y *= inv; q4.z *= inv; q4.w *= inv;
    {
        float p = warp_sum(q4.x * q4.x + q4.y * q4.y + q4.z * q4.z + q4.w * q4.w);
        if (lane == 0) s_wv[wid] = p;
    }

    // --- stage avg_attn into smem, then reset scratch for the next replay
    #pragma unroll
    for (int j = 0; j < 4; j++) {
        float4 v = reinterpret_cast<const float4*>(g_avg)[b * (LC / 4) + tid + j * 256];
        reinterpret_cast<float4*>(s_attn)[tid + j * 256] = v;
    }
    __syncthreads();
    #pragma unroll
    for (int j = 0; j < 4; j++)
        reinterpret_cast<float4*>(g_avg)[b * (LC / 4) + tid + j * 256] = zero4;
    reinterpret_cast<float4*>(g_qvec)[b * (DD / 4) + tid] = zero4;

    // qnorm lives in warp0 lane0's register
    float qn = 0.0f;
    if (wid == 0) {
        float v = (lane < 8) ? s_wv[lane] : 0.0f;
        v = warp_sum(v);
        if (lane == 0) qn = fmaxf(sqrtf(v), EPS);
    }

    // --- 5 argmax rounds: packed (value, LC-1-i) keys, 64-bit max reduce ---
    for (int k = 0; k < TOPK; k++) {
        unsigned long long best = 0ull;
        #pragma unroll
        for (int j = 0; j < 16; j++) {
            int i = tid + j * 256;
            unsigned long long key =
                ((unsigned long long)ord(s_attn[i]) << 32) | (unsigned)(LC - 1 - i);
            if (key > best) best = key;
        }
        best = warp_max64(best);
        if (lane == 0) s_key[wid] = best;
        __syncthreads();
        if (wid == 0) {
            unsigned long long v = (lane < 8) ? s_key[lane] : 0ull;
            v = warp_max64(v);
            if (lane == 0) {
                int i = LC - 1 - (int)(unsigned)(v & 0xffffffffu);
                s_top[k] = i;
                s_attn[i] = -1.0f;   // below any real value under ord()
            }
        }
        __syncthreads();
    }

    // --- gather all 5 context rows (batched, one DRAM round-trip) ---------
    float4 cv[TOPK];
    #pragma unroll
    for (int k = 0; k < TOPK; k++)
        cv[k] = reinterpret_cast<const float4*>(ctx)
                    [((size_t)b * LC + (size_t)s_top[k]) * (DD / 4) + tid];

    // --- all 10 partial reductions, single barrier -------------------------
    #pragma unroll
    for (int k = 0; k < TOPK; k++) {
        float d = warp_sum(cv[k].x * q4.x + cv[k].y * q4.y +
                           cv[k].z * q4.z + cv[k].w * q4.w);
        float n = warp_sum(cv[k].x * cv[k].x + cv[k].y * cv[k].y +
                           cv[k].z * cv[k].z + cv[k].w * cv[k].w);
        if (lane == 0) { s_red[k][wid] = d; s_red[TOPK + k][wid] = n; }
    }
    __syncthreads();

    if (wid == 0) {
        float loss = 0.0f;
        #pragma unroll
        for (int k = 0; k < TOPK; k++) {
            float dd = warp_sum((lane < 8) ? s_red[k][lane] : 0.0f);
            float nn = warp_sum((lane < 8) ? s_red[TOPK + k][lane] : 0.0f);
            if (lane == 0)
                loss += 1.0f - dd / (qn * fmaxf(sqrtf(nn), EPS));
        }
        if (lane == 0) {
            atomicAdd(&g_loss_sum, loss);
            __threadfence();
            int t = atomicAdd(&g_done, 1);
            if (t == NB - 1) {
                float total = atomicAdd(&g_loss_sum, 0.0f);  // coherent read
                out[0] = total / (float)(NB * TOPK);
                g_loss_sum = 0.0f;   // reset for next replay
                g_done     = 0;
            }
        }
    }
}

// ---------------------------------------------------------------------------
extern "C" void kernel_launch(void* const* d_in, const int* in_sizes, int n_in,
                              void* d_out, int out_size) {
    const float* q   = (const float*)d_in[0];  // question_emb  [8,128,1024]
    const float* ctx = (const float*)d_in[1];  // context_emb   [8,4096,1024]
    const float* w   = (const float*)d_in[2];  // cross_attn    [8,16,128,4096]

    fused_reduce<<<1024 + 64, 256>>>((const float4*)w, (const float4*)q);
    tail_kernel<<<NB, 256>>>(ctx, (float*)d_out);
}